// round 1
// baseline (speedup 1.0000x reference)
#include <cuda_runtime.h>
#include <math.h>

// ---------------- problem constants ----------------
#define NTOK 16384      // 8 * 2048 tokens
#define SEQ  2048
#define BATCH 8
#define DIMC 384
#define QKV3 1152
#define HID  1536
#define HEADS 6
#define HDIM 64
#define EPSV 1e-5f

// ---------------- scratch (device globals; no allocation allowed) ----------------
__device__ float g_h[(size_t)NTOK * DIMC];     // LN output
__device__ float g_qkv[(size_t)NTOK * QKV3];   // qkv projections
__device__ float g_o[(size_t)NTOK * DIMC];     // attention output
__device__ float g_a[(size_t)NTOK * HID];      // mlp scratch A
__device__ float g_b2[(size_t)NTOK * HID];     // mlp scratch B

__device__ __forceinline__ float gelu_exact(float x) {
    return 0.5f * x * (1.0f + erff(x * 0.7071067811865475f));
}

// ---------------- LayerNorm: one token per block, 128 threads ----------------
__global__ void ln_kernel(const float* __restrict__ x, const float* __restrict__ w,
                          const float* __restrict__ b, float* __restrict__ out)
{
    const int t = blockIdx.x;
    const float* xr = x + (size_t)t * DIMC;
    float* orow = out + (size_t)t * DIMC;
    const int tid = threadIdx.x;

    float v0 = xr[tid], v1 = xr[tid + 128], v2 = xr[tid + 256];
    float s = v0 + v1 + v2;
    float q = v0 * v0 + v1 * v1 + v2 * v2;
    #pragma unroll
    for (int off = 16; off > 0; off >>= 1) {
        s += __shfl_xor_sync(0xffffffffu, s, off);
        q += __shfl_xor_sync(0xffffffffu, q, off);
    }
    __shared__ float ss[4], qq[4];
    if ((tid & 31) == 0) { ss[tid >> 5] = s; qq[tid >> 5] = q; }
    __syncthreads();
    s = ss[0] + ss[1] + ss[2] + ss[3];
    q = qq[0] + qq[1] + qq[2] + qq[3];
    const float mean = s * (1.0f / DIMC);
    const float var  = q * (1.0f / DIMC) - mean * mean;
    const float inv  = rsqrtf(var + EPSV);

    orow[tid]       = (v0 - mean) * inv * w[tid]       + b[tid];
    orow[tid + 128] = (v1 - mean) * inv * w[tid + 128] + b[tid + 128];
    orow[tid + 256] = (v2 - mean) * inv * w[tid + 256] + b[tid + 256];
}

// ---------------- GEMM: C[m,n] = epilogue( sum_k A[m,k] * W[n,k] ) ----------------
// MODE 0: + bias (bias may be null)
// MODE 1: gelu(acc + bias)
// MODE 2: res + (acc + bias) * gamma       (residual + layer-scale)
// Tiles: 128x128x16, 256 threads, 8x8 per thread (split 4+4 to avoid LDS conflicts).
// All M, N, K here are multiples of 128/16 -> no bounds checks.
template<int MODE>
__global__ void __launch_bounds__(256) gemm_nt(
    const float* __restrict__ A, const float* __restrict__ W,
    const float* __restrict__ bias, const float* __restrict__ res,
    const float* __restrict__ gamma, float* __restrict__ C,
    int N, int K)
{
    __shared__ float As[16][128];
    __shared__ float Bs[16][128];

    const int tid = threadIdx.x;
    const int tx = tid & 15;
    const int ty = tid >> 4;
    const size_t bm = (size_t)blockIdx.y * 128;
    const size_t bn = (size_t)blockIdx.x * 128;

    const float* Ab = A + bm * (size_t)K;
    const float* Wb = W + bn * (size_t)K;

    float acc[8][8];
    #pragma unroll
    for (int i = 0; i < 8; i++)
        #pragma unroll
        for (int j = 0; j < 8; j++) acc[i][j] = 0.0f;

    const int r0 = tid >> 2;           // 0..63
    const int r1 = r0 + 64;            // 64..127
    const int kc = (tid & 3) << 2;     // 0,4,8,12

    for (int kt = 0; kt < K; kt += 16) {
        float4 va0 = *(const float4*)(Ab + (size_t)r0 * K + kt + kc);
        float4 va1 = *(const float4*)(Ab + (size_t)r1 * K + kt + kc);
        float4 vb0 = *(const float4*)(Wb + (size_t)r0 * K + kt + kc);
        float4 vb1 = *(const float4*)(Wb + (size_t)r1 * K + kt + kc);

        As[kc + 0][r0] = va0.x; As[kc + 1][r0] = va0.y; As[kc + 2][r0] = va0.z; As[kc + 3][r0] = va0.w;
        As[kc + 0][r1] = va1.x; As[kc + 1][r1] = va1.y; As[kc + 2][r1] = va1.z; As[kc + 3][r1] = va1.w;
        Bs[kc + 0][r0] = vb0.x; Bs[kc + 1][r0] = vb0.y; Bs[kc + 2][r0] = vb0.z; Bs[kc + 3][r0] = vb0.w;
        Bs[kc + 0][r1] = vb1.x; Bs[kc + 1][r1] = vb1.y; Bs[kc + 2][r1] = vb1.z; Bs[kc + 3][r1] = vb1.w;
        __syncthreads();

        #pragma unroll
        for (int k = 0; k < 16; k++) {
            float4 aA = *(const float4*)&As[k][ty * 4];
            float4 aB = *(const float4*)&As[k][64 + ty * 4];
            float4 bA = *(const float4*)&Bs[k][tx * 4];
            float4 bB = *(const float4*)&Bs[k][64 + tx * 4];
            float af[8] = {aA.x, aA.y, aA.z, aA.w, aB.x, aB.y, aB.z, aB.w};
            float bf[8] = {bA.x, bA.y, bA.z, bA.w, bB.x, bB.y, bB.z, bB.w};
            #pragma unroll
            for (int i = 0; i < 8; i++)
                #pragma unroll
                for (int j = 0; j < 8; j++)
                    acc[i][j] = fmaf(af[i], bf[j], acc[i][j]);
        }
        __syncthreads();
    }

    // epilogue
    #pragma unroll
    for (int i = 0; i < 8; i++) {
        const size_t m = bm + (size_t)((i < 4) ? (ty * 4 + i) : (64 + ty * 4 + (i - 4)));
        float* Crow = C + m * (size_t)N;
        const float* Rrow = (MODE == 2) ? (res + m * (size_t)N) : nullptr;
        #pragma unroll
        for (int half = 0; half < 2; half++) {
            const int n0 = (int)bn + half * 64 + tx * 4;
            float v[4];
            #pragma unroll
            for (int j = 0; j < 4; j++) {
                const int jj = half * 4 + j;
                const int n = n0 + j;
                float a = acc[i][jj];
                if (MODE == 0) {
                    if (bias) a += bias[n];
                } else if (MODE == 1) {
                    a = gelu_exact(a + bias[n]);
                } else {
                    a = Rrow[n] + (a + bias[n]) * gamma[n];
                }
                v[j] = a;
            }
            *(float4*)(Crow + n0) = make_float4(v[0], v[1], v[2], v[3]);
        }
    }
}

// ---------------- Flash attention ----------------
// grid (32 q-tiles, 6 heads, 8 batch), 256 threads (16x16), dynamic smem.
// Q tile 64x64 (pre-scaled), stream KV in 64-row tiles, online softmax.
#define AP 68   // smem pitch (floats); 68/4=17 -> conflict-free float4 rows
#define ATTN_SMEM ((3 * 64 * AP + 128) * (int)sizeof(float))

__global__ void __launch_bounds__(256) attn_kernel(const float* __restrict__ qkv,
                                                   float* __restrict__ og)
{
    extern __shared__ float sm[];
    float* Qs   = sm;                 // [64][AP]
    float* Ks   = Qs + 64 * AP;       // [64][AP], reused as P after S compute
    float* Vs   = Ks + 64 * AP;       // [64][AP]
    float* mrow = Vs + 64 * AP;       // [64]
    float* lrow = mrow + 64;          // [64]

    const int b  = blockIdx.z;
    const int h  = blockIdx.y;
    const int qt = blockIdx.x;
    const int tid = threadIdx.x;
    const int tx = tid & 15;          // col group
    const int ty = tid >> 4;          // row group

    const size_t base = (size_t)b * SEQ * QKV3;

    // load Q tile (scaled by 1/sqrt(64))
    #pragma unroll
    for (int i = 0; i < 4; i++) {
        const int id = tid + i * 256;          // 0..1023
        const int row = id >> 4;               // 0..63
        const int c4 = (id & 15) << 2;         // 0..60
        float4 v = *(const float4*)(qkv + base + (size_t)(qt * 64 + row) * QKV3 + h * HDIM + c4);
        *(float4*)(Qs + row * AP + c4) = make_float4(v.x * 0.125f, v.y * 0.125f, v.z * 0.125f, v.w * 0.125f);
    }
    if (tid < 64) { mrow[tid] = -3.0e38f; lrow[tid] = 0.0f; }

    float4 oacc[4] = {};  // rows ty*4+i, dims tx*4..tx*4+3

    for (int kt = 0; kt < 32; kt++) {
        __syncthreads();   // prev iteration done with Ks(P)/Vs; Q/stats init visible after next sync
        #pragma unroll
        for (int i = 0; i < 4; i++) {
            const int id = tid + i * 256;
            const int row = id >> 4;
            const int c4 = (id & 15) << 2;
            const size_t gb = base + (size_t)(kt * 64 + row) * QKV3 + h * HDIM + c4;
            *(float4*)(Ks + row * AP + c4) = *(const float4*)(qkv + gb + 384);   // K
            *(float4*)(Vs + row * AP + c4) = *(const float4*)(qkv + gb + 768);   // V
        }
        __syncthreads();

        // S[4][4] = Q(rows) . K(cols)
        float s[4][4] = {};
        #pragma unroll
        for (int kb = 0; kb < 16; kb++) {
            float4 qv[4], kv[4];
            #pragma unroll
            for (int i = 0; i < 4; i++) qv[i] = *(const float4*)(Qs + (ty * 4 + i) * AP + kb * 4);
            #pragma unroll
            for (int j = 0; j < 4; j++) kv[j] = *(const float4*)(Ks + (tx * 4 + j) * AP + kb * 4);
            #pragma unroll
            for (int i = 0; i < 4; i++)
                #pragma unroll
                for (int j = 0; j < 4; j++)
                    s[i][j] += qv[i].x * kv[j].x + qv[i].y * kv[j].y + qv[i].z * kv[j].z + qv[i].w * kv[j].w;
        }

        // online softmax stats
        float mnew[4], corr[4], rsum[4];
        #pragma unroll
        for (int i = 0; i < 4; i++) {
            float rm = s[i][0];
            #pragma unroll
            for (int j = 1; j < 4; j++) rm = fmaxf(rm, s[i][j]);
            #pragma unroll
            for (int off = 8; off > 0; off >>= 1)
                rm = fmaxf(rm, __shfl_xor_sync(0xffffffffu, rm, off, 16));
            const float mo = mrow[ty * 4 + i];
            const float mn = fmaxf(mo, rm);
            mnew[i] = mn;
            corr[i] = __expf(mo - mn);
            float rs = 0.0f;
            #pragma unroll
            for (int j = 0; j < 4; j++) { s[i][j] = __expf(s[i][j] - mn); rs += s[i][j]; }
            #pragma unroll
            for (int off = 8; off > 0; off >>= 1)
                rs += __shfl_xor_sync(0xffffffffu, rs, off, 16);
            rsum[i] = rs;
            oacc[i].x *= corr[i]; oacc[i].y *= corr[i]; oacc[i].z *= corr[i]; oacc[i].w *= corr[i];
        }
        __syncthreads();   // all done reading Ks (as K) and mrow

        // write P over Ks; tx==0 updates stats
        #pragma unroll
        for (int i = 0; i < 4; i++)
            *(float4*)(Ks + (ty * 4 + i) * AP + tx * 4) = make_float4(s[i][0], s[i][1], s[i][2], s[i][3]);
        if (tx == 0) {
            #pragma unroll
            for (int i = 0; i < 4; i++) {
                const int r = ty * 4 + i;
                mrow[r] = mnew[i];
                lrow[r] = lrow[r] * corr[i] + rsum[i];
            }
        }
        __syncthreads();

        // O += P * V
        #pragma unroll
        for (int cb = 0; cb < 16; cb++) {
            float4 pv[4];
            #pragma unroll
            for (int i = 0; i < 4; i++) pv[i] = *(const float4*)(Ks + (ty * 4 + i) * AP + cb * 4);
            const float4 vv0 = *(const float4*)(Vs + (cb * 4 + 0) * AP + tx * 4);
            const float4 vv1 = *(const float4*)(Vs + (cb * 4 + 1) * AP + tx * 4);
            const float4 vv2 = *(const float4*)(Vs + (cb * 4 + 2) * AP + tx * 4);
            const float4 vv3 = *(const float4*)(Vs + (cb * 4 + 3) * AP + tx * 4);
            #pragma unroll
            for (int i = 0; i < 4; i++) {
                oacc[i].x = fmaf(pv[i].x, vv0.x, oacc[i].x);
                oacc[i].y = fmaf(pv[i].x, vv0.y, oacc[i].y);
                oacc[i].z = fmaf(pv[i].x, vv0.z, oacc[i].z);
                oacc[i].w = fmaf(pv[i].x, vv0.w, oacc[i].w);
                oacc[i].x = fmaf(pv[i].y, vv1.x, oacc[i].x);
                oacc[i].y = fmaf(pv[i].y, vv1.y, oacc[i].y);
                oacc[i].z = fmaf(pv[i].y, vv1.z, oacc[i].z);
                oacc[i].w = fmaf(pv[i].y, vv1.w, oacc[i].w);
                oacc[i].x = fmaf(pv[i].z, vv2.x, oacc[i].x);
                oacc[i].y = fmaf(pv[i].z, vv2.y, oacc[i].y);
                oacc[i].z = fmaf(pv[i].z, vv2.z, oacc[i].z);
                oacc[i].w = fmaf(pv[i].z, vv2.w, oacc[i].w);
                oacc[i].x = fmaf(pv[i].w, vv3.x, oacc[i].x);
                oacc[i].y = fmaf(pv[i].w, vv3.y, oacc[i].y);
                oacc[i].z = fmaf(pv[i].w, vv3.z, oacc[i].z);
                oacc[i].w = fmaf(pv[i].w, vv3.w, oacc[i].w);
            }
        }
    }

    // finalize: divide by l, write O[b, n, h*64 + d]
    #pragma unroll
    for (int i = 0; i < 4; i++) {
        const int r = ty * 4 + i;
        const float linv = 1.0f / lrow[r];
        const int n = qt * 64 + r;
        float4 out4 = make_float4(oacc[i].x * linv, oacc[i].y * linv, oacc[i].z * linv, oacc[i].w * linv);
        *(float4*)(og + ((size_t)(b * SEQ + n)) * DIMC + h * HDIM + tx * 4) = out4;
    }
}

// ---------------- launch ----------------
extern "C" void kernel_launch(void* const* d_in, const int* in_sizes, int n_in,
                              void* d_out, int out_size)
{
    const float* x      = (const float*)d_in[0];
    const float* qkv_w  = (const float*)d_in[1];
    const float* qkv_b  = (const float*)d_in[2];
    const float* proj_w = (const float*)d_in[3];
    const float* proj_b = (const float*)d_in[4];
    const float* fc1_w  = (const float*)d_in[5];
    const float* fc1_b  = (const float*)d_in[6];
    const float* eye1_w = (const float*)d_in[7];
    const float* eye2_w = (const float*)d_in[8];
    const float* fc2_w  = (const float*)d_in[9];
    const float* fc2_b  = (const float*)d_in[10];
    const float* n1w    = (const float*)d_in[11];
    const float* n1b    = (const float*)d_in[12];
    const float* n2w    = (const float*)d_in[13];
    const float* n2b    = (const float*)d_in[14];
    const float* ls1    = (const float*)d_in[15];
    const float* ls2    = (const float*)d_in[16];
    float* out = (float*)d_out;

    float *ph, *pqkv, *po, *pa, *pb;
    cudaGetSymbolAddress((void**)&ph,   g_h);
    cudaGetSymbolAddress((void**)&pqkv, g_qkv);
    cudaGetSymbolAddress((void**)&po,   g_o);
    cudaGetSymbolAddress((void**)&pa,   g_a);
    cudaGetSymbolAddress((void**)&pb,   g_b2);

    cudaFuncSetAttribute(attn_kernel, cudaFuncAttributeMaxDynamicSharedMemorySize, ATTN_SMEM);

    const dim3 blk(256);

    // 1. h = LN1(x)
    ln_kernel<<<NTOK, 128>>>(x, n1w, n1b, ph);
    // 2. qkv = h @ qkv_w^T + qkv_b
    gemm_nt<0><<<dim3(QKV3 / 128, NTOK / 128), blk>>>(ph, qkv_w, qkv_b, nullptr, nullptr, pqkv, QKV3, DIMC);
    // 3. o = attention(qkv)
    attn_kernel<<<dim3(SEQ / 64, HEADS, BATCH), blk, ATTN_SMEM>>>(pqkv, po);
    // 4. out = x + (o @ proj_w^T + proj_b) * ls1
    gemm_nt<2><<<dim3(DIMC / 128, NTOK / 128), blk>>>(po, proj_w, proj_b, x, ls1, out, DIMC, DIMC);
    // 5. h = LN2(out)
    ln_kernel<<<NTOK, 128>>>(out, n2w, n2b, ph);
    // 6. a = gelu(h @ fc1_w^T + fc1_b)
    gemm_nt<1><<<dim3(HID / 128, NTOK / 128), blk>>>(ph, fc1_w, fc1_b, nullptr, nullptr, pa, HID, DIMC);
    // 7. b = a @ eye1_w^T
    gemm_nt<0><<<dim3(HID / 128, NTOK / 128), blk>>>(pa, eye1_w, nullptr, nullptr, nullptr, pb, HID, HID);
    // 8. a = b @ eye2_w^T
    gemm_nt<0><<<dim3(HID / 128, NTOK / 128), blk>>>(pb, eye2_w, nullptr, nullptr, nullptr, pa, HID, HID);
    // 9. out = out + (a @ fc2_w^T + fc2_b) * ls2
    gemm_nt<2><<<dim3(DIMC / 128, NTOK / 128), blk>>>(pa, fc2_w, fc2_b, out, ls2, out, DIMC, HID);
}

// round 2
// speedup vs baseline: 6.6368x; 6.6368x over previous
#include <cuda_runtime.h>
#include <cuda_bf16.h>
#include <math.h>
#include <stdint.h>

// ---------------- problem constants ----------------
#define NTOK 16384      // 8 * 2048 tokens
#define SEQ  2048
#define BATCH 8
#define DIMC 384
#define QKV3 1152
#define HID  1536
#define HEADS 6
#define HDIM 64
#define EPSV 1e-5f

// ---------------- scratch (device globals) ----------------
__device__ __nv_bfloat16 g_hb  [(size_t)NTOK * DIMC];   // LN output (bf16)
__device__ __nv_bfloat16 g_qkvb[(size_t)NTOK * QKV3];   // qkv (bf16)
__device__ __nv_bfloat16 g_ob  [(size_t)NTOK * DIMC];   // attention out (bf16)
__device__ __nv_bfloat16 g_ab  [(size_t)NTOK * HID];    // mlp scratch A (bf16)
__device__ __nv_bfloat16 g_bb  [(size_t)NTOK * HID];    // mlp scratch B (bf16)
// bf16 weights
__device__ __nv_bfloat16 g_wqkv[(size_t)QKV3 * DIMC];
__device__ __nv_bfloat16 g_wproj[(size_t)DIMC * DIMC];
__device__ __nv_bfloat16 g_wfc1[(size_t)HID * DIMC];
__device__ __nv_bfloat16 g_weye1[(size_t)HID * HID];
__device__ __nv_bfloat16 g_weye2[(size_t)HID * HID];
__device__ __nv_bfloat16 g_wfc2[(size_t)DIMC * HID];

// ---------------- helpers ----------------
__device__ __forceinline__ uint32_t smem_u32(const void* p) {
    return (uint32_t)__cvta_generic_to_shared(p);
}
__device__ __forceinline__ void ldm_x4(uint32_t& r0, uint32_t& r1, uint32_t& r2, uint32_t& r3, uint32_t a) {
    asm volatile("ldmatrix.sync.aligned.m8n8.x4.shared.b16 {%0,%1,%2,%3},[%4];\n"
                 : "=r"(r0), "=r"(r1), "=r"(r2), "=r"(r3) : "r"(a));
}
__device__ __forceinline__ void ldm_x4_t(uint32_t& r0, uint32_t& r1, uint32_t& r2, uint32_t& r3, uint32_t a) {
    asm volatile("ldmatrix.sync.aligned.m8n8.x4.trans.shared.b16 {%0,%1,%2,%3},[%4];\n"
                 : "=r"(r0), "=r"(r1), "=r"(r2), "=r"(r3) : "r"(a));
}
__device__ __forceinline__ void mma_bf16(float c[4], const uint32_t a[4], const uint32_t b[2]) {
    asm volatile(
        "mma.sync.aligned.m16n8k16.row.col.f32.bf16.bf16.f32 "
        "{%0,%1,%2,%3},{%4,%5,%6,%7},{%8,%9},{%0,%1,%2,%3};\n"
        : "+f"(c[0]), "+f"(c[1]), "+f"(c[2]), "+f"(c[3])
        : "r"(a[0]), "r"(a[1]), "r"(a[2]), "r"(a[3]), "r"(b[0]), "r"(b[1]));
}
__device__ __forceinline__ uint32_t packbf(float lo, float hi) {
    __nv_bfloat162 h = __floats2bfloat162_rn(lo, hi);
    return *reinterpret_cast<uint32_t*>(&h);
}
__device__ __forceinline__ float gelu_exact(float x) {
    return 0.5f * x * (1.0f + erff(x * 0.7071067811865475f));
}

// ---------------- fp32 -> bf16 convert ----------------
__global__ void f2bf_kernel(const float* __restrict__ in, __nv_bfloat16* __restrict__ out, int n) {
    int i = (blockIdx.x * blockDim.x + threadIdx.x) * 4;
    if (i < n) {
        float4 v = *(const float4*)(in + i);
        *(__nv_bfloat162*)(out + i)     = __floats2bfloat162_rn(v.x, v.y);
        *(__nv_bfloat162*)(out + i + 2) = __floats2bfloat162_rn(v.z, v.w);
    }
}

// ---------------- LayerNorm -> bf16 ----------------
__global__ void ln_kernel(const float* __restrict__ x, const float* __restrict__ w,
                          const float* __restrict__ b, __nv_bfloat16* __restrict__ out)
{
    const int t = blockIdx.x;
    const float* xr = x + (size_t)t * DIMC;
    __nv_bfloat16* orow = out + (size_t)t * DIMC;
    const int tid = threadIdx.x;

    float v0 = xr[tid], v1 = xr[tid + 128], v2 = xr[tid + 256];
    float s = v0 + v1 + v2;
    float q = v0 * v0 + v1 * v1 + v2 * v2;
    #pragma unroll
    for (int off = 16; off > 0; off >>= 1) {
        s += __shfl_xor_sync(0xffffffffu, s, off);
        q += __shfl_xor_sync(0xffffffffu, q, off);
    }
    __shared__ float ss[4], qq[4];
    if ((tid & 31) == 0) { ss[tid >> 5] = s; qq[tid >> 5] = q; }
    __syncthreads();
    s = ss[0] + ss[1] + ss[2] + ss[3];
    q = qq[0] + qq[1] + qq[2] + qq[3];
    const float mean = s * (1.0f / DIMC);
    const float var  = q * (1.0f / DIMC) - mean * mean;
    const float inv  = rsqrtf(var + EPSV);

    orow[tid]       = __float2bfloat16((v0 - mean) * inv * w[tid]       + b[tid]);
    orow[tid + 128] = __float2bfloat16((v1 - mean) * inv * w[tid + 128] + b[tid + 128]);
    orow[tid + 256] = __float2bfloat16((v2 - mean) * inv * w[tid + 256] + b[tid + 256]);
}

// ---------------- bf16 tensor-core GEMM: C = epi(A @ W^T) ----------------
// A [M,K] bf16 row-major, W [N,K] bf16 row-major.
// MODE 0: +bias (nullable). MODE 1: gelu(+bias). MODE 2: res + (+bias)*gamma.
// OUTBF: 1 -> bf16 output, 0 -> fp32 output.
// Block tile 128x128x32(halves), 256 threads, warp grid 4(m)x2(n), warp tile 32x64.
#define GP 40   // smem pitch in halves (32 data + 8 pad) -> conflict-free ldmatrix
template<int MODE, int OUTBF>
__global__ void __launch_bounds__(256) gemm_bf16(
    const __nv_bfloat16* __restrict__ A, const __nv_bfloat16* __restrict__ W,
    const float* __restrict__ bias, const float* __restrict__ res,
    const float* __restrict__ gamma, void* __restrict__ Cout,
    int N, int K)
{
    __shared__ __align__(16) __nv_bfloat16 sA[2][128 * GP];
    __shared__ __align__(16) __nv_bfloat16 sB[2][128 * GP];

    const int tid  = threadIdx.x;
    const int lane = tid & 31;
    const int warp = tid >> 5;
    const int wm = warp >> 1;    // 0..3
    const int wn = warp & 1;     // 0..1
    const size_t bm = (size_t)blockIdx.y * 128;
    const size_t bn = (size_t)blockIdx.x * 128;

    const __nv_bfloat16* Ab = A + bm * (size_t)K;
    const __nv_bfloat16* Wb = W + bn * (size_t)K;

    float c[2][8][4];
    #pragma unroll
    for (int i = 0; i < 2; i++)
        #pragma unroll
        for (int j = 0; j < 8; j++)
            #pragma unroll
            for (int k = 0; k < 4; k++) c[i][j][k] = 0.0f;

    // loader: 512 16B-chunks per tile per matrix; thread handles chunks tid, tid+256
    const int lrow = tid >> 2;          // 0..63
    const int loff = (tid & 3) * 8;     // halves: 0,8,16,24

    uint4 a0v, a1v, b0v, b1v;
    // prologue: tile 0
    a0v = *(const uint4*)(Ab + (size_t)lrow * K + loff);
    a1v = *(const uint4*)(Ab + (size_t)(lrow + 64) * K + loff);
    b0v = *(const uint4*)(Wb + (size_t)lrow * K + loff);
    b1v = *(const uint4*)(Wb + (size_t)(lrow + 64) * K + loff);
    *(uint4*)(&sA[0][lrow * GP + loff])        = a0v;
    *(uint4*)(&sA[0][(lrow + 64) * GP + loff]) = a1v;
    *(uint4*)(&sB[0][lrow * GP + loff])        = b0v;
    *(uint4*)(&sB[0][(lrow + 64) * GP + loff]) = b1v;
    __syncthreads();

    const int nk = K >> 5;
    int buf = 0;
    for (int t = 0; t < nk; t++) {
        if (t + 1 < nk) {
            const int kt = (t + 1) << 5;
            a0v = *(const uint4*)(Ab + (size_t)lrow * K + kt + loff);
            a1v = *(const uint4*)(Ab + (size_t)(lrow + 64) * K + kt + loff);
            b0v = *(const uint4*)(Wb + (size_t)lrow * K + kt + loff);
            b1v = *(const uint4*)(Wb + (size_t)(lrow + 64) * K + kt + loff);
        }
        const uint32_t abase = smem_u32(&sA[buf][0]);
        const uint32_t bbase = smem_u32(&sB[buf][0]);
        #pragma unroll
        for (int kk = 0; kk < 2; kk++) {
            uint32_t af[2][4];
            #pragma unroll
            for (int mt = 0; mt < 2; mt++) {
                uint32_t addr = abase +
                    (((wm * 32 + mt * 16 + (lane & 15)) * GP) + kk * 16 + ((lane >> 4) << 3)) * 2;
                ldm_x4(af[mt][0], af[mt][1], af[mt][2], af[mt][3], addr);
            }
            uint32_t bf[8][2];
            #pragma unroll
            for (int p = 0; p < 4; p++) {
                uint32_t addr = bbase +
                    (((wn * 64 + p * 16 + ((lane >> 4) << 3) + (lane & 7)) * GP) +
                     kk * 16 + (((lane >> 3) & 1) << 3)) * 2;
                ldm_x4(bf[2 * p][0], bf[2 * p][1], bf[2 * p + 1][0], bf[2 * p + 1][1], addr);
            }
            #pragma unroll
            for (int mt = 0; mt < 2; mt++)
                #pragma unroll
                for (int nt = 0; nt < 8; nt++)
                    mma_bf16(c[mt][nt], af[mt], bf[nt]);
        }
        if (t + 1 < nk) {
            const int nb = buf ^ 1;
            *(uint4*)(&sA[nb][lrow * GP + loff])        = a0v;
            *(uint4*)(&sA[nb][(lrow + 64) * GP + loff]) = a1v;
            *(uint4*)(&sB[nb][lrow * GP + loff])        = b0v;
            *(uint4*)(&sB[nb][(lrow + 64) * GP + loff]) = b1v;
        }
        __syncthreads();
        buf ^= 1;
    }

    // ---------------- epilogue ----------------
    const int r = lane >> 2;
    const int c2 = (lane & 3) * 2;
    #pragma unroll
    for (int mt = 0; mt < 2; mt++) {
        const size_t row0 = bm + wm * 32 + mt * 16 + r;
        const size_t row1 = row0 + 8;
        #pragma unroll
        for (int nt = 0; nt < 8; nt++) {
            const int col = (int)bn + wn * 64 + nt * 8 + c2;
            float b0 = 0.f, b1 = 0.f;
            if (MODE != 0 || bias) { b0 = bias[col]; b1 = bias[col + 1]; }
            float v00 = c[mt][nt][0] + b0, v01 = c[mt][nt][1] + b1;
            float v10 = c[mt][nt][2] + b0, v11 = c[mt][nt][3] + b1;
            if (MODE == 1) {
                v00 = gelu_exact(v00); v01 = gelu_exact(v01);
                v10 = gelu_exact(v10); v11 = gelu_exact(v11);
            } else if (MODE == 2) {
                const float g0 = gamma[col], g1 = gamma[col + 1];
                v00 = res[row0 * N + col] + v00 * g0;
                v01 = res[row0 * N + col + 1] + v01 * g1;
                v10 = res[row1 * N + col] + v10 * g0;
                v11 = res[row1 * N + col + 1] + v11 * g1;
            }
            if (OUTBF) {
                __nv_bfloat16* C = (__nv_bfloat16*)Cout;
                *(__nv_bfloat162*)(C + row0 * N + col) = __floats2bfloat162_rn(v00, v01);
                *(__nv_bfloat162*)(C + row1 * N + col) = __floats2bfloat162_rn(v10, v11);
            } else {
                float* C = (float*)Cout;
                *(float2*)(C + row0 * N + col) = make_float2(v00, v01);
                *(float2*)(C + row1 * N + col) = make_float2(v10, v11);
            }
        }
    }
}

// ---------------- bf16 flash attention ----------------
// grid (32 q-tiles, 6 heads, 8 batch), 128 threads = 4 warps.
// Q tile 64x64, KV streamed in 64-row tiles. Warp w owns q rows w*16..w*16+15.
#define AQP 72   // smem pitch (halves): 64 data + 8 pad
__global__ void __launch_bounds__(128) attn_bf16(const __nv_bfloat16* __restrict__ qkv,
                                                 __nv_bfloat16* __restrict__ og)
{
    __shared__ __align__(16) __nv_bfloat16 Qs[64 * AQP];
    __shared__ __align__(16) __nv_bfloat16 Ks[64 * AQP];
    __shared__ __align__(16) __nv_bfloat16 Vs[64 * AQP];

    const int b  = blockIdx.z;
    const int h  = blockIdx.y;
    const int qt = blockIdx.x;
    const int tid  = threadIdx.x;
    const int lane = tid & 31;
    const int warp = tid >> 5;
    const size_t base = (size_t)b * SEQ * QKV3;

    // load Q tile
    #pragma unroll
    for (int i = 0; i < 4; i++) {
        const int cidx = tid + i * 128;           // 0..511
        const int row = cidx >> 3;
        const int off = (cidx & 7) * 8;
        *(uint4*)(Qs + row * AQP + off) =
            *(const uint4*)(qkv + base + (size_t)(qt * 64 + row) * QKV3 + h * HDIM + off);
    }

    float m_run[2] = { -1e30f, -1e30f };
    float l_run[2] = { 0.0f, 0.0f };
    float o[8][4];
    #pragma unroll
    for (int i = 0; i < 8; i++)
        #pragma unroll
        for (int j = 0; j < 4; j++) o[i][j] = 0.0f;

    const uint32_t qb = smem_u32(Qs);
    const uint32_t kb = smem_u32(Ks);
    const uint32_t vb = smem_u32(Vs);

    for (int kt = 0; kt < 32; kt++) {
        __syncthreads();
        #pragma unroll
        for (int i = 0; i < 4; i++) {
            const int cidx = tid + i * 128;
            const int row = cidx >> 3;
            const int off = (cidx & 7) * 8;
            const size_t g = base + (size_t)(kt * 64 + row) * QKV3 + h * HDIM + off;
            *(uint4*)(Ks + row * AQP + off) = *(const uint4*)(qkv + g + DIMC);
            *(uint4*)(Vs + row * AQP + off) = *(const uint4*)(qkv + g + 2 * DIMC);
        }
        __syncthreads();

        // S = Q @ K^T  (fp32 accum)
        float s[8][4];
        #pragma unroll
        for (int i = 0; i < 8; i++)
            #pragma unroll
            for (int j = 0; j < 4; j++) s[i][j] = 0.0f;

        #pragma unroll
        for (int ks = 0; ks < 4; ks++) {
            uint32_t a[4];
            uint32_t aaddr = qb + (((warp * 16 + (lane & 15)) * AQP) + ks * 16 + ((lane >> 4) << 3)) * 2;
            ldm_x4(a[0], a[1], a[2], a[3], aaddr);
            uint32_t bbv[8][2];
            #pragma unroll
            for (int p = 0; p < 4; p++) {
                uint32_t baddr = kb + (((p * 16 + ((lane >> 4) << 3) + (lane & 7)) * AQP) +
                                       ks * 16 + (((lane >> 3) & 1) << 3)) * 2;
                ldm_x4(bbv[2 * p][0], bbv[2 * p][1], bbv[2 * p + 1][0], bbv[2 * p + 1][1], baddr);
            }
            #pragma unroll
            for (int nt = 0; nt < 8; nt++) mma_bf16(s[nt], a, bbv[nt]);
        }

        // online softmax (scale 1/8 folded in)
        #pragma unroll
        for (int rr = 0; rr < 2; rr++) {
            float rmax = s[0][rr * 2];
            #pragma unroll
            for (int nt = 0; nt < 8; nt++) {
                rmax = fmaxf(rmax, s[nt][rr * 2]);
                rmax = fmaxf(rmax, s[nt][rr * 2 + 1]);
            }
            rmax = fmaxf(rmax, __shfl_xor_sync(0xffffffffu, rmax, 1));
            rmax = fmaxf(rmax, __shfl_xor_sync(0xffffffffu, rmax, 2));
            const float mn = fmaxf(m_run[rr], rmax * 0.125f);
            const float corr = __expf(m_run[rr] - mn);
            m_run[rr] = mn;
            float rs = 0.0f;
            #pragma unroll
            for (int nt = 0; nt < 8; nt++) {
                float p0 = __expf(s[nt][rr * 2] * 0.125f - mn);
                float p1 = __expf(s[nt][rr * 2 + 1] * 0.125f - mn);
                s[nt][rr * 2] = p0; s[nt][rr * 2 + 1] = p1;
                rs += p0 + p1;
            }
            rs += __shfl_xor_sync(0xffffffffu, rs, 1);
            rs += __shfl_xor_sync(0xffffffffu, rs, 2);
            l_run[rr] = l_run[rr] * corr + rs;
            #pragma unroll
            for (int dt = 0; dt < 8; dt++) {
                o[dt][rr * 2] *= corr;
                o[dt][rr * 2 + 1] *= corr;
            }
        }

        // O += P @ V
        #pragma unroll
        for (int j = 0; j < 4; j++) {
            uint32_t aP[4];
            aP[0] = packbf(s[2 * j][0], s[2 * j][1]);
            aP[1] = packbf(s[2 * j][2], s[2 * j][3]);
            aP[2] = packbf(s[2 * j + 1][0], s[2 * j + 1][1]);
            aP[3] = packbf(s[2 * j + 1][2], s[2 * j + 1][3]);
            uint32_t bv[8][2];
            #pragma unroll
            for (int p = 0; p < 4; p++) {
                uint32_t baddr = vb + (((j * 16 + (lane & 7) + (((lane >> 3) & 1) << 3)) * AQP) +
                                       p * 16 + ((lane >> 4) << 3)) * 2;
                ldm_x4_t(bv[2 * p][0], bv[2 * p][1], bv[2 * p + 1][0], bv[2 * p + 1][1], baddr);
            }
            #pragma unroll
            for (int dt = 0; dt < 8; dt++) mma_bf16(o[dt], aP, bv[dt]);
        }
    }

    // normalize + write bf16 output [tok][DIMC]
    const float linv0 = 1.0f / l_run[0];
    const float linv1 = 1.0f / l_run[1];
    const int row0 = qt * 64 + warp * 16 + (lane >> 2);
    __nv_bfloat16* out0 = og + ((size_t)(b * SEQ) + row0) * DIMC + h * HDIM + (lane & 3) * 2;
    #pragma unroll
    for (int dt = 0; dt < 8; dt++) {
        *(__nv_bfloat162*)(out0 + dt * 8) =
            __floats2bfloat162_rn(o[dt][0] * linv0, o[dt][1] * linv0);
        *(__nv_bfloat162*)(out0 + 8 * DIMC + dt * 8) =
            __floats2bfloat162_rn(o[dt][2] * linv1, o[dt][3] * linv1);
    }
}

// ---------------- launch ----------------
extern "C" void kernel_launch(void* const* d_in, const int* in_sizes, int n_in,
                              void* d_out, int out_size)
{
    const float* x      = (const float*)d_in[0];
    const float* qkv_w  = (const float*)d_in[1];
    const float* qkv_b  = (const float*)d_in[2];
    const float* proj_w = (const float*)d_in[3];
    const float* proj_b = (const float*)d_in[4];
    const float* fc1_w  = (const float*)d_in[5];
    const float* fc1_b  = (const float*)d_in[6];
    const float* eye1_w = (const float*)d_in[7];
    const float* eye2_w = (const float*)d_in[8];
    const float* fc2_w  = (const float*)d_in[9];
    const float* fc2_b  = (const float*)d_in[10];
    const float* n1w    = (const float*)d_in[11];
    const float* n1b    = (const float*)d_in[12];
    const float* n2w    = (const float*)d_in[13];
    const float* n2b    = (const float*)d_in[14];
    const float* ls1    = (const float*)d_in[15];
    const float* ls2    = (const float*)d_in[16];
    float* out = (float*)d_out;

    __nv_bfloat16 *hb, *qkvb, *ob, *ab, *bb;
    __nv_bfloat16 *wqkv, *wproj, *wfc1, *weye1, *weye2, *wfc2;
    cudaGetSymbolAddress((void**)&hb,   g_hb);
    cudaGetSymbolAddress((void**)&qkvb, g_qkvb);
    cudaGetSymbolAddress((void**)&ob,   g_ob);
    cudaGetSymbolAddress((void**)&ab,   g_ab);
    cudaGetSymbolAddress((void**)&bb,   g_bb);
    cudaGetSymbolAddress((void**)&wqkv,  g_wqkv);
    cudaGetSymbolAddress((void**)&wproj, g_wproj);
    cudaGetSymbolAddress((void**)&wfc1,  g_wfc1);
    cudaGetSymbolAddress((void**)&weye1, g_weye1);
    cudaGetSymbolAddress((void**)&weye2, g_weye2);
    cudaGetSymbolAddress((void**)&wfc2,  g_wfc2);

    // weight conversions (cheap; graph-captured, deterministic)
    const int CT = 256;
    f2bf_kernel<<<(QKV3 * DIMC / 4 + CT - 1) / CT, CT>>>(qkv_w,  wqkv,  QKV3 * DIMC);
    f2bf_kernel<<<(DIMC * DIMC / 4 + CT - 1) / CT, CT>>>(proj_w, wproj, DIMC * DIMC);
    f2bf_kernel<<<(HID * DIMC / 4 + CT - 1) / CT, CT>>>(fc1_w,  wfc1,  HID * DIMC);
    f2bf_kernel<<<(HID * HID / 4 + CT - 1) / CT, CT>>>(eye1_w, weye1, HID * HID);
    f2bf_kernel<<<(HID * HID / 4 + CT - 1) / CT, CT>>>(eye2_w, weye2, HID * HID);
    f2bf_kernel<<<(DIMC * HID / 4 + CT - 1) / CT, CT>>>(fc2_w,  wfc2,  DIMC * HID);

    const dim3 blk(256);

    // 1. h = LN1(x)  -> bf16
    ln_kernel<<<NTOK, 128>>>(x, n1w, n1b, hb);
    // 2. qkv = h @ qkv_w^T + qkv_b  -> bf16
    gemm_bf16<0, 1><<<dim3(QKV3 / 128, NTOK / 128), blk>>>(hb, wqkv, qkv_b, nullptr, nullptr, qkvb, QKV3, DIMC);
    // 3. o = attention(qkv) -> bf16
    attn_bf16<<<dim3(SEQ / 64, HEADS, BATCH), 128>>>(qkvb, ob);
    // 4. out = x + (o @ proj_w^T + proj_b) * ls1  -> fp32
    gemm_bf16<2, 0><<<dim3(DIMC / 128, NTOK / 128), blk>>>(ob, wproj, proj_b, x, ls1, out, DIMC, DIMC);
    // 5. h = LN2(out) -> bf16
    ln_kernel<<<NTOK, 128>>>(out, n2w, n2b, hb);
    // 6. a = gelu(h @ fc1_w^T + fc1_b) -> bf16
    gemm_bf16<1, 1><<<dim3(HID / 128, NTOK / 128), blk>>>(hb, wfc1, fc1_b, nullptr, nullptr, ab, HID, DIMC);
    // 7. b = a @ eye1_w^T -> bf16
    gemm_bf16<0, 1><<<dim3(HID / 128, NTOK / 128), blk>>>(ab, weye1, nullptr, nullptr, nullptr, bb, HID, HID);
    // 8. a = b @ eye2_w^T -> bf16
    gemm_bf16<0, 1><<<dim3(HID / 128, NTOK / 128), blk>>>(bb, weye2, nullptr, nullptr, nullptr, ab, HID, HID);
    // 9. out = out + (a @ fc2_w^T + fc2_b) * ls2 -> fp32
    gemm_bf16<2, 0><<<dim3(DIMC / 128, NTOK / 128), blk>>>(ab, wfc2, fc2_b, out, ls2, out, DIMC, HID);
}